// round 9
// baseline (speedup 1.0000x reference)
#include <cuda_runtime.h>
#include <cuda_fp16.h>
#include <math.h>

#define MAXB 16384

// Scratch + accumulators (no allocations allowed; device globals).
__device__ float2 g_de[MAXB];          // exact {d^2, e} per row (+pads)
__device__ uint4  g_jp[MAXB / 4];      // fp16 packed: {d2(r0,r1), -e(r0,r1), d2(r2,r3), -e(r2,r3)}
__device__ double g_sum;               // sum of max(x,-1) over all slots
__device__ unsigned int g_tick;        // completion counter (self-wrapping)
__device__ unsigned int g_arrive;      // barrier arrivals (self-wrapping)
__device__ unsigned int g_release;     // barrier epoch (monotonic)

constexpr int TILE    = 256;
constexpr int THREADS = 256;

// fp32: a ^ (b & 0x80000000)  (one LOP3)
__device__ __forceinline__ float sflip(float a, float b) {
    unsigned int r;
    asm("lop3.b32 %0, %1, %2, %3, 0x78;"
        : "=r"(r) : "r"(__float_as_uint(a)), "r"(__float_as_uint(b)),
          "n"(0x80000000u));
    return __uint_as_float(r);
}
// fp16x2 per-half sign flip: a ^ (b & 0x80008000)
__device__ __forceinline__ unsigned int sflip2(unsigned int a, unsigned int b) {
    unsigned int r;
    asm("lop3.b32 %0, %1, %2, %3, 0x78;"
        : "=r"(r) : "r"(a), "r"(b), "n"(0x80008000u));
    return r;
}
__device__ __forceinline__ __half2 u2h(unsigned int u) {
    __half2 h; *reinterpret_cast<unsigned int*>(&h) = u; return h;
}
__device__ __forceinline__ unsigned int h2u(__half2 h) {
    return *reinterpret_cast<unsigned int*>(&h);
}

// ---------------------------------------------------------------------------
// One kernel, two phases separated by a device-wide spin barrier:
//   Phase A: rows' {d^2, e} computed once into g_de (fp32) + g_jp (fp16 pack).
//            Pads: {+inf, 60000} -> every pad slot nets 0 (see nslots).
//   Phase B: triangle-tiled 256x256 bricks; off-diagonal bricks in fp16x2
//            (2 pairs/instr: HADD2/LOP3/HMAX2/HADD2, fp32 spill per 16 iters);
//            diagonal bricks exact fp32 with j>i predication.
//   relu(x+1) = max(x,-1) + 1 with x = sign(d2_j - d2_i) * (e_i - e_j);
//   the +1-per-slot total (exact, host-computed) is added at the end.
//   Last-finishing block writes out[0]. All counters self-reset (graph-safe).
// Residency: __launch_bounds__(256,4) -> >=4 blocks/SM -> 592 slots >= NB,
// so all blocks co-reside and the spin barrier cannot deadlock.
// ---------------------------------------------------------------------------
__global__ __launch_bounds__(THREADS, 4) void fused_kernel(
    const float* __restrict__ energies,
    const float* __restrict__ pv,
    const float* __restrict__ pt,
    int B, int P, int T, int NB, double nslots, double invcnt,
    float* __restrict__ out)
{
    int t   = threadIdx.x;
    int bid = blockIdx.x;
    int Bpad = T * TILE;

    // ---- Phase A: prep (2 rows per participating thread) ----
    auto row_de = [&](int row) -> float2 {
        if (row >= B) return make_float2(INFINITY, 60000.0f);  // pad row
        float s = 0.0f;
        if (P == 16) {
            const float4* pv4 = (const float4*)(pv + (size_t)row * 16);
            const float4* pt4 = (const float4*)pt;
            #pragma unroll
            for (int q = 0; q < 4; q++) {
                float4 v = pv4[q];
                float4 w = pt4[q];
                float a = v.x - w.x, b = v.y - w.y;
                float c = v.z - w.z, d = v.w - w.w;
                s = fmaf(a, a, fmaf(b, b, fmaf(c, c, fmaf(d, d, s))));
            }
        } else {
            for (int q = 0; q < P; q++) {
                float df = pv[(size_t)row * P + q] - pt[q];
                s = fmaf(df, df, s);
            }
        }
        return make_float2(s, energies[row]);
    };

    int p = bid * THREADS + t;
    if (p < Bpad / 2) {
        float2 r0 = row_de(2 * p);
        float2 r1 = row_de(2 * p + 1);
        g_de[2 * p]     = r0;
        g_de[2 * p + 1] = r1;
        uint2 pk;
        pk.x = h2u(__floats2half2_rn(r0.x, r1.x));    // d2 pair
        pk.y = h2u(__floats2half2_rn(-r0.y, -r1.y));  // -e pair
        ((uint2*)g_jp)[p] = pk;
    }

    // ---- device-wide barrier (epoch-based, replay-safe) ----
    if (t == 0) {
        unsigned int my = *((volatile unsigned int*)&g_release);
        __threadfence();
        unsigned int old = atomicInc(&g_arrive, (unsigned int)(NB - 1));
        if (old == (unsigned int)(NB - 1)) {
            __threadfence();
            atomicAdd(&g_release, 1u);
        } else {
            while (*((volatile unsigned int*)&g_release) == my) __nanosleep(32);
        }
        __threadfence();
    }
    __syncthreads();

    // ---- Phase B: triangle decode ----
    float tf = 2.0f * T + 1.0f;
    int ti = (int)floorf((tf - sqrtf(fmaxf(tf * tf - 8.0f * (float)bid, 0.0f))) * 0.5f);
    if (ti < 0) ti = 0;
    if (ti > T - 1) ti = T - 1;
    while (ti > 0 && (ti * T - ti * (ti - 1) / 2) > bid) ti--;
    while (((ti + 1) * T - (ti + 1) * ti / 2) <= bid) ti++;
    int tj = ti + (bid - (ti * T - ti * (ti - 1) / 2));

    __shared__ uint4  jt[TILE / 4];     // fp16 packed j tile
    __shared__ float2 stage[TILE];      // fp32 j tile (diagonal bricks only)
    __shared__ float  ssum[THREADS / 32];

    bool diag = (ti == tj);
    if (t < TILE / 4) jt[t] = g_jp[tj * (TILE / 4) + t];
    if (diag) stage[t] = g_de[tj * TILE + t];
    float2 mi = g_de[ti * TILE + t];
    float di = mi.x, ei = mi.y;
    __syncthreads();

    float facc0 = 0.0f, facc1 = 0.0f;

    if (!diag) {
        // ---- fp16x2 SIMD path: 2 pairs / instruction ----
        unsigned int ndi2 = h2u(__float2half2_rn(-di));
        unsigned int ei2  = h2u(__float2half2_rn(ei));
        const __half2 neg1 = __floats2half2_rn(-1.0f, -1.0f);

        #pragma unroll
        for (int kk = 0; kk < (TILE / 4) / 16; kk++) {
            __half2 a01 = __floats2half2_rn(0.0f, 0.0f);
            __half2 a23 = __floats2half2_rn(0.0f, 0.0f);
            #pragma unroll
            for (int u = 0; u < 16; u++) {
                uint4 q = jt[kk * 16 + u];                    // LDS.128 -> 4 pairs
                unsigned int dd01 = h2u(__hadd2(u2h(q.x), u2h(ndi2)));
                unsigned int dd23 = h2u(__hadd2(u2h(q.z), u2h(ndi2)));
                unsigned int de01 = h2u(__hadd2(u2h(ei2), u2h(q.y)));
                unsigned int de23 = h2u(__hadd2(u2h(ei2), u2h(q.w)));
                __half2 x01 = u2h(sflip2(de01, dd01));        // s*(e_i - e_j)
                __half2 x23 = u2h(sflip2(de23, dd23));
                a01 = __hadd2(a01, __hmax2(x01, neg1));       // relu(x+1) - 1
                a23 = __hadd2(a23, __hmax2(x23, neg1));
            }
            float2 f01 = __half22float2(a01);                 // fp32 spill
            float2 f23 = __half22float2(a23);
            facc0 += f01.x + f23.x;
            facc1 += f01.y + f23.y;
        }
    } else {
        // ---- diagonal brick: exact fp32, only local j > local i ----
        #pragma unroll 8
        for (int j = 0; j < TILE; j++) {
            float2 s = stage[j];
            float dd = s.x - di;
            float de = ei - s.y;
            float x = sflip(de, dd);
            if (j > t) facc0 += fmaxf(x, -1.0f);
        }
    }

    float acc = facc0 + facc1;

    // --- block reduction ---
    #pragma unroll
    for (int o = 16; o > 0; o >>= 1)
        acc += __shfl_down_sync(0xFFFFFFFFu, acc, o);

    int w = t >> 5, l = t & 31;
    if (l == 0) ssum[w] = acc;
    __syncthreads();

    // --- global accumulation + last-block epilogue ---
    if (t == 0) {
        float a = 0.0f;
        #pragma unroll
        for (int k = 0; k < THREADS / 32; k++) a += ssum[k];
        atomicAdd(&g_sum, (double)a);
        __threadfence();
        unsigned int old = atomicInc(&g_tick, (unsigned int)(NB - 1));
        if (old == (unsigned int)(NB - 1)) {
            unsigned long long bits =
                atomicExch((unsigned long long*)&g_sum, 0ull); // read + reset
            out[0] = (float)((__longlong_as_double(bits) + nslots) * invcnt);
        }
    }
}

// ---------------------------------------------------------------------------
extern "C" void kernel_launch(void* const* d_in, const int* in_sizes, int n_in,
                              void* d_out, int out_size) {
    const float* energies = (const float*)d_in[0];   // (B, 1)
    const float* pv       = (const float*)d_in[1];   // (B, P)
    const float* pt       = (const float*)d_in[2];   // (P,)
    float* out            = (float*)d_out;

    int B = in_sizes[0];
    int P = in_sizes[2];
    if (B > MAXB) B = MAXB;

    int T  = (B + TILE - 1) / TILE;
    int NB = T * (T + 1) / 2;

    // exact +1-per-slot total; pad rows net 0 except pad-pad slots in the
    // final diagonal brick (value 0 but +1 counted) -> subtract them.
    double npad = (double)(T * TILE - B);
    double nslots = (double)(T * (T - 1) / 2) * (double)TILE * (double)TILE
                  + (double)T * (double)(TILE * (TILE - 1) / 2)
                  - npad * (npad - 1.0) * 0.5;

    double cnt = (double)B * (double)(B - 1) * 0.5;
    if (cnt < 1.0) cnt = 1.0;

    fused_kernel<<<NB, THREADS>>>(energies, pv, pt, B, P, T, NB,
                                  nslots, 1.0 / cnt, out);
}

// round 10
// speedup vs baseline: 1.3375x; 1.3375x over previous
#include <cuda_runtime.h>
#include <cuda_fp16.h>
#include <math.h>

// Accumulators (no allocations allowed; device globals, zero-initialized).
__device__ double g_sum;          // sum of max(x,-1) over all evaluated slots
__device__ unsigned int g_tick;   // block completion counter (self-wrapping)

constexpr int TILE    = 256;
constexpr int THREADS = 256;

// fp16x2 per-half sign flip: a ^ (b & 0x80008000)  (one LOP3)
__device__ __forceinline__ unsigned int sflip2(unsigned int a, unsigned int b) {
    unsigned int r;
    asm("lop3.b32 %0, %1, %2, %3, 0x78;"
        : "=r"(r) : "r"(a), "r"(b), "n"(0x80008000u));
    return r;
}
__device__ __forceinline__ __half2 u2h(unsigned int u) {
    __half2 h; *reinterpret_cast<unsigned int*>(&h) = u; return h;
}
__device__ __forceinline__ unsigned int h2u(__half2 h) {
    return *reinterpret_cast<unsigned int*>(&h);
}

// ---------------------------------------------------------------------------
// Single fused kernel, triangle-tiled 256x256 bricks (T*(T+1)/2 blocks):
//   * {d^2, e} computed per block for its own rows (overlaps across blocks;
//     no global barrier -- R9 showed a grid barrier serializes + burns L2
//     atomics). Pads: {+inf, 60000} -> every pad slot nets 0 (see nslots).
//   * value per unordered pair: relu(x+1) = max(x,-1)+1,
//     x = sign(d2_j - d2_i) * (e_i - e_j)  (per-half sign-bit XOR).
//   * whole pair phase in fp16x2: per iter 2x LDS.128 (8 d2 + 8 -e halves)
//     -> 8 pairs in ~22 instr; prefetch next vectors; 4 acc chains; fp32
//     spill every 16 iters. Diagonal bricks add a j>i lane mask via
//     __hgt2 on fp16 indices + __hfma2.
//   * +1-per-slot total (exact, host-computed) added at the end.
//   * last-finishing block writes out[0] (self-resetting, graph-replayable).
// ---------------------------------------------------------------------------
__global__ __launch_bounds__(THREADS) void fused_kernel(
    const float* __restrict__ energies,
    const float* __restrict__ pv,
    const float* __restrict__ pt,
    int B, int P, int T, int NB, double nslots, double invcnt,
    float* __restrict__ out)
{
    int t   = threadIdx.x;
    int bid = blockIdx.x;

    // --- triangle decode: bid -> (ti, tj), ti <= tj ---
    float tf = 2.0f * T + 1.0f;
    int ti = (int)floorf((tf - sqrtf(fmaxf(tf * tf - 8.0f * (float)bid, 0.0f))) * 0.5f);
    if (ti < 0) ti = 0;
    if (ti > T - 1) ti = T - 1;
    while (ti > 0 && (ti * T - ti * (ti - 1) / 2) > bid) ti--;
    while (((ti + 1) * T - (ti + 1) * ti / 2) <= bid) ti++;
    int tj = ti + (bid - (ti * T - ti * (ti - 1) / 2));
    bool diag = (ti == tj);

    __shared__ __half jd[TILE];          // d2_j   (fp16)
    __shared__ __half je[TILE];          // -e_j   (fp16)
    __shared__ float  ssum[THREADS / 32];

    // --- per-row prep {d^2, e} ---
    auto row_de = [&](int row) -> float2 {
        if (row >= B) return make_float2(INFINITY, 60000.0f);   // pad row
        float s = 0.0f;
        if (P == 16) {
            const float4* pv4 = (const float4*)(pv + (size_t)row * 16);
            const float4* pt4 = (const float4*)pt;
            #pragma unroll
            for (int q = 0; q < 4; q++) {
                float4 v = pv4[q];
                float4 w = pt4[q];
                float a = v.x - w.x, b = v.y - w.y;
                float c = v.z - w.z, d = v.w - w.w;
                s = fmaf(a, a, fmaf(b, b, fmaf(c, c, fmaf(d, d, s))));
            }
        } else {
            for (int q = 0; q < P; q++) {
                float df = pv[(size_t)row * P + q] - pt[q];
                s = fmaf(df, df, s);
            }
        }
        return make_float2(s, energies[row]);
    };

    float2 mi = row_de(ti * TILE + t);                       // my i row
    float2 mj = diag ? mi : row_de(tj * TILE + t);           // my j row
    jd[t] = __float2half_rn(mj.x);
    je[t] = __float2half_rn(-mj.y);
    __syncthreads();

    unsigned int ndi2 = h2u(__float2half2_rn(-mi.x));   // (-d2_i, -d2_i)
    unsigned int ei2  = h2u(__float2half2_rn(mi.y));    // ( e_i ,  e_i )
    const __half2 neg1 = __floats2half2_rn(-1.0f, -1.0f);

    const uint4* jd4 = (const uint4*)jd;   // 8 halves per uint4
    const uint4* je4 = (const uint4*)je;

    float facc = 0.0f;

    if (!diag) {
        // ---- off-diagonal: 8 pairs / iter, 32 iters ----
        uint4 qd = jd4[0], qe = je4[0];
        #pragma unroll
        for (int kk = 0; kk < 2; kk++) {                 // fp32 spill chunks
            __half2 a0 = u2h(0u), a1 = u2h(0u), a2 = u2h(0u), a3 = u2h(0u);
            #pragma unroll
            for (int u = 0; u < 16; u++) {
                int idx = kk * 16 + u;
                uint4 nd, ne;
                if (idx < 31) { nd = jd4[idx + 1]; ne = je4[idx + 1]; }
                unsigned int dd0 = h2u(__hadd2(u2h(qd.x), u2h(ndi2)));
                unsigned int dd1 = h2u(__hadd2(u2h(qd.y), u2h(ndi2)));
                unsigned int dd2 = h2u(__hadd2(u2h(qd.z), u2h(ndi2)));
                unsigned int dd3 = h2u(__hadd2(u2h(qd.w), u2h(ndi2)));
                unsigned int de0 = h2u(__hadd2(u2h(ei2), u2h(qe.x)));
                unsigned int de1 = h2u(__hadd2(u2h(ei2), u2h(qe.y)));
                unsigned int de2 = h2u(__hadd2(u2h(ei2), u2h(qe.z)));
                unsigned int de3 = h2u(__hadd2(u2h(ei2), u2h(qe.w)));
                a0 = __hadd2(a0, __hmax2(u2h(sflip2(de0, dd0)), neg1));
                a1 = __hadd2(a1, __hmax2(u2h(sflip2(de1, dd1)), neg1));
                a2 = __hadd2(a2, __hmax2(u2h(sflip2(de2, dd2)), neg1));
                a3 = __hadd2(a3, __hmax2(u2h(sflip2(de3, dd3)), neg1));
                qd = nd; qe = ne;
            }
            float2 f0 = __half22float2(a0), f1 = __half22float2(a1);
            float2 f2 = __half22float2(a2), f3 = __half22float2(a3);
            facc += ((f0.x + f0.y) + (f1.x + f1.y))
                  + ((f2.x + f2.y) + (f3.x + f3.y));
        }
    } else {
        // ---- diagonal: j>i lane mask via fp16 index compare ----
        const __half2 tt    = __float2half2_rn((float)t);
        const __half2 eight = __float2half2_rn(8.0f);
        __half2 jv0 = __floats2half2_rn(0.0f, 1.0f);
        __half2 jv1 = __floats2half2_rn(2.0f, 3.0f);
        __half2 jv2 = __floats2half2_rn(4.0f, 5.0f);
        __half2 jv3 = __floats2half2_rn(6.0f, 7.0f);
        #pragma unroll
        for (int kk = 0; kk < 2; kk++) {
            __half2 a0 = u2h(0u), a1 = u2h(0u), a2 = u2h(0u), a3 = u2h(0u);
            #pragma unroll
            for (int u = 0; u < 16; u++) {
                int idx = kk * 16 + u;
                uint4 qd = jd4[idx], qe = je4[idx];
                unsigned int dd0 = h2u(__hadd2(u2h(qd.x), u2h(ndi2)));
                unsigned int dd1 = h2u(__hadd2(u2h(qd.y), u2h(ndi2)));
                unsigned int dd2 = h2u(__hadd2(u2h(qd.z), u2h(ndi2)));
                unsigned int dd3 = h2u(__hadd2(u2h(qd.w), u2h(ndi2)));
                unsigned int de0 = h2u(__hadd2(u2h(ei2), u2h(qe.x)));
                unsigned int de1 = h2u(__hadd2(u2h(ei2), u2h(qe.y)));
                unsigned int de2 = h2u(__hadd2(u2h(ei2), u2h(qe.z)));
                unsigned int de3 = h2u(__hadd2(u2h(ei2), u2h(qe.w)));
                __half2 c0 = __hmax2(u2h(sflip2(de0, dd0)), neg1);
                __half2 c1 = __hmax2(u2h(sflip2(de1, dd1)), neg1);
                __half2 c2 = __hmax2(u2h(sflip2(de2, dd2)), neg1);
                __half2 c3 = __hmax2(u2h(sflip2(de3, dd3)), neg1);
                a0 = __hfma2(__hgt2(jv0, tt), c0, a0);
                a1 = __hfma2(__hgt2(jv1, tt), c1, a1);
                a2 = __hfma2(__hgt2(jv2, tt), c2, a2);
                a3 = __hfma2(__hgt2(jv3, tt), c3, a3);
                jv0 = __hadd2(jv0, eight);
                jv1 = __hadd2(jv1, eight);
                jv2 = __hadd2(jv2, eight);
                jv3 = __hadd2(jv3, eight);
            }
            float2 f0 = __half22float2(a0), f1 = __half22float2(a1);
            float2 f2 = __half22float2(a2), f3 = __half22float2(a3);
            facc += ((f0.x + f0.y) + (f1.x + f1.y))
                  + ((f2.x + f2.y) + (f3.x + f3.y));
        }
    }

    // --- block reduction ---
    #pragma unroll
    for (int o = 16; o > 0; o >>= 1)
        facc += __shfl_down_sync(0xFFFFFFFFu, facc, o);

    int w = t >> 5, l = t & 31;
    if (l == 0) ssum[w] = facc;
    __syncthreads();

    // --- global accumulation + last-block epilogue ---
    if (t == 0) {
        float a = 0.0f;
        #pragma unroll
        for (int k = 0; k < THREADS / 32; k++) a += ssum[k];
        atomicAdd(&g_sum, (double)a);
        __threadfence();
        unsigned int old = atomicInc(&g_tick, (unsigned int)(NB - 1));
        if (old == (unsigned int)(NB - 1)) {
            unsigned long long bits =
                atomicExch((unsigned long long*)&g_sum, 0ull); // read + reset
            out[0] = (float)((__longlong_as_double(bits) + nslots) * invcnt);
        }
    }
}

// ---------------------------------------------------------------------------
extern "C" void kernel_launch(void* const* d_in, const int* in_sizes, int n_in,
                              void* d_out, int out_size) {
    const float* energies = (const float*)d_in[0];   // (B, 1)
    const float* pv       = (const float*)d_in[1];   // (B, P)
    const float* pt       = (const float*)d_in[2];   // (P,)
    float* out            = (float*)d_out;

    int B = in_sizes[0];
    int P = in_sizes[2];

    int T  = (B + TILE - 1) / TILE;
    int NB = T * (T + 1) / 2;

    // exact +1-per-slot total; pad rows net 0 except pad-pad slots in the
    // final diagonal brick (value 0 but +1 counted) -> subtract them.
    double npad = (double)(T * TILE - B);
    double nslots = (double)(T * (T - 1) / 2) * (double)TILE * (double)TILE
                  + (double)T * (double)(TILE * (TILE - 1) / 2)
                  - npad * (npad - 1.0) * 0.5;

    double cnt = (double)B * (double)(B - 1) * 0.5;
    if (cnt < 1.0) cnt = 1.0;

    fused_kernel<<<NB, THREADS>>>(energies, pv, pt, B, P, T, NB,
                                  nslots, 1.0 / cnt, out);
}